// round 10
// baseline (speedup 1.0000x reference)
#include <cuda_runtime.h>
#include <cuda_bf16.h>
#include <stdint.h>

// ---------------- problem constants (fixed shapes from reference) -------------
#define KB   32          // batches
#define KS   1024        // sequence
#define KD   768         // feature dim
#define KNL  16          // label values
#define KC   32          // k-chunk (bf16 elements)
#define NCHUNK (KD / KC) // 24
#define PITCH 80         // smem row pitch bytes (64B data + 16B pad -> conflict-free ldmatrix)
#define BUFB  (128 * PITCH)
#define SCALE_F (1.0f / (0.7f * 27.712812921102035f))   // 1/(T*sqrt(D))

// ---------------- device scratch (no allocations allowed) ---------------------
__device__ __align__(256) __nv_bfloat16 g_feat[(size_t)KB * KS * KD]; // 48 MB bf16 copy
__device__ int   g_lab[KB * KS];   // widened labels (int32 regardless of input dtype)
__device__ int   g_cnt[KB][KNL];
__device__ float g_part[KB * 8];

// ---------------- kernel 0: label dtype detect + widen ------------------------
// The reference builds labels with .astype(jnp.int64) under JAX; with x64
// disabled (default) that is silently int32. Handle BOTH dtypes:
//  - scan odd 32-bit words of the first KB*KS words (safe bound for int32 buf):
//    int64 -> hi words of labels 0..15 -> all zero; int32 -> random labels,
//    some nonzero with overwhelming probability.
__global__ void k_preplab(const uint32_t* __restrict__ w) {
    __shared__ int s_is32;
    const int t = threadIdx.x;
    if (t == 0) s_is32 = 0;
    __syncthreads();
    int any = 0;
    for (int j = t; j < KB * KS / 2; j += 1024) any |= (int)w[2 * j + 1];
    if (any) atomicOr(&s_is32, 1);
    __syncthreads();
    const int is32 = s_is32;
    for (int i = t; i < KB * KS; i += 1024)
        g_lab[i] = is32 ? (int)w[i] : (int)w[2 * i];
}

// ---------------- kernel 1: fp32 -> bf16 conversion ---------------------------
__global__ void k_convert(const float* __restrict__ f) {
    size_t i  = (size_t)blockIdx.x * blockDim.x + threadIdx.x;
    size_t n4 = (size_t)KB * KS * KD / 4;
    if (i < n4) {
        float4 v = reinterpret_cast<const float4*>(f)[i];
        __nv_bfloat162 lo = __floats2bfloat162_rn(v.x, v.y);
        __nv_bfloat162 hi = __floats2bfloat162_rn(v.z, v.w);
        uint2 pk;
        pk.x = *reinterpret_cast<uint32_t*>(&lo);
        pk.y = *reinterpret_cast<uint32_t*>(&hi);
        reinterpret_cast<uint2*>(g_feat)[i] = pk;
    }
}

// ---------------- kernel 2: per-batch label histogram -------------------------
__global__ void k_count() {
    __shared__ int cnt[KNL];
    int b = blockIdx.x;
    if (threadIdx.x < KNL) cnt[threadIdx.x] = 0;
    __syncthreads();
    for (int i = threadIdx.x; i < KS; i += blockDim.x)
        atomicAdd(&cnt[g_lab[b * KS + i] & (KNL - 1)], 1);
    __syncthreads();
    if (threadIdx.x < KNL) g_cnt[b][threadIdx.x] = cnt[threadIdx.x];
}

// ---------------- PTX helpers -------------------------------------------------
__device__ __forceinline__ void cp16(uint32_t dst, const void* src) {
    asm volatile("cp.async.cg.shared.global [%0], [%1], 16;\n"
                 :: "r"(dst), "l"(src) : "memory");
}
__device__ __forceinline__ void ldsm4(uint32_t* r, uint32_t addr) {
    asm volatile("ldmatrix.sync.aligned.m8n8.x4.shared.b16 {%0,%1,%2,%3}, [%4];\n"
                 : "=r"(r[0]), "=r"(r[1]), "=r"(r[2]), "=r"(r[3]) : "r"(addr));
}
__device__ __forceinline__ void mma_bf16(float* d, const uint32_t* a, const uint32_t* b) {
    asm volatile("mma.sync.aligned.m16n8k16.row.col.f32.bf16.bf16.f32 "
                 "{%0,%1,%2,%3}, {%4,%5,%6,%7}, {%8,%9}, {%0,%1,%2,%3};\n"
                 : "+f"(d[0]), "+f"(d[1]), "+f"(d[2]), "+f"(d[3])
                 : "r"(a[0]), "r"(a[1]), "r"(a[2]), "r"(a[3]),
                   "r"(b[0]), "r"(b[1]));
}

// ---------------- kernel 3: fused GEMM + SupCon epilogue ----------------------
// grid = KB*8 CTAs; CTA = (batch b, 128-row i-tile). 8 warps as 4(m) x 2(n).
// Loops over 8 j-tiles of 128; each j-tile: K=768 bf16 GEMM (cp.async double
// buffered), then masked epilogue into per-anchor register accumulators.
__global__ __launch_bounds__(256, 2) void k_main() {
    __shared__ __align__(16) unsigned char sAraw[2 * BUFB];   // 20 KB
    __shared__ __align__(16) unsigned char sBraw[2 * BUFB];   // 20 KB
    __shared__ int   slab[128];
    __shared__ float sred[128][2][3];
    __shared__ float sred2[128];

    const int tid  = threadIdx.x;
    const int lane = tid & 31;
    const int warp = tid >> 5;
    const int wm   = warp >> 1;     // 0..3 -> 32-row band
    const int wn   = warp & 1;      // 0..1 -> 64-col band
    const int cta  = blockIdx.x;
    const int b    = cta >> 3;
    const int i0   = (cta & 7) * 128;

    const uint32_t sA_u = (uint32_t)__cvta_generic_to_shared(sAraw);
    const uint32_t sB_u = (uint32_t)__cvta_generic_to_shared(sBraw);
    const __nv_bfloat16* fb = g_feat + (size_t)b * KS * KD;
    const int*           lb = g_lab  + b * KS;

    // Per-thread anchor-row metadata (4 rows: r = mi*2 + h)
    int   rlab[4];
    float rc[4];
    #pragma unroll
    for (int mi = 0; mi < 2; ++mi)
        #pragma unroll
        for (int h = 0; h < 2; ++h) {
            int r  = mi * 2 + h;
            int ig = i0 + wm * 32 + mi * 16 + h * 8 + (lane >> 2);
            int l  = lb[ig];
            rlab[r] = l;
            int nn  = KS - g_cnt[b][l & (KNL - 1)];
            rc[r]   = (nn > 0) ? (SCALE_F / (float)nn) : 0.0f;
        }

    float accN[4] = {0, 0, 0, 0};   // sum over negatives of exp(sim/num_neg)
    float accP[4] = {0, 0, 0, 0};   // sum of raw dots for positives j>i
    float accL[4] = {0, 0, 0, 0};   // count of positives j>i

    #pragma unroll 1
    for (int jt = 0; jt < 8; ++jt) {
        const int j0 = jt * 128;
        __syncthreads();                       // protect slab & smem bufs from prev iter
        if (tid < 128) slab[tid] = lb[j0 + tid];

        float d[2][8][4];
        #pragma unroll
        for (int mi = 0; mi < 2; ++mi)
            #pragma unroll
            for (int ni = 0; ni < 8; ++ni)
                #pragma unroll
                for (int q = 0; q < 4; ++q) d[mi][ni][q] = 0.0f;

        auto stage = [&](int c) {
            const int buf = c & 1;
            #pragma unroll
            for (int q = 0; q < 2; ++q) {      // A: 512 16B granules / 256 thr
                int gi = tid + q * 256;
                int row = gi >> 2, g = gi & 3;
                cp16(sA_u + buf * BUFB + row * PITCH + g * 16,
                     fb + (size_t)(i0 + row) * KD + c * KC + g * 8);
            }
            #pragma unroll
            for (int q = 0; q < 2; ++q) {      // B
                int gi = tid + q * 256;
                int row = gi >> 2, g = gi & 3;
                cp16(sB_u + buf * BUFB + row * PITCH + g * 16,
                     fb + (size_t)(j0 + row) * KD + c * KC + g * 8);
            }
            asm volatile("cp.async.commit_group;\n" ::: "memory");
        };

        stage(0);
        stage(1);

        #pragma unroll 1
        for (int c = 0; c < NCHUNK; ++c) {
            if (c < NCHUNK - 1) asm volatile("cp.async.wait_group 1;\n" ::: "memory");
            else                asm volatile("cp.async.wait_group 0;\n" ::: "memory");
            __syncthreads();
            const uint32_t bA = sA_u + (c & 1) * BUFB;
            const uint32_t bB = sB_u + (c & 1) * BUFB;
            #pragma unroll
            for (int ks = 0; ks < 2; ++ks) {
                uint32_t afr[2][4];
                #pragma unroll
                for (int mi = 0; mi < 2; ++mi) {
                    int row = wm * 32 + mi * 16 + (lane & 7) + ((lane >> 3) & 1) * 8;
                    int g   = 2 * ks + (lane >> 4);
                    ldsm4(afr[mi], bA + row * PITCH + g * 16);
                }
                uint32_t bfr[4][4];
                #pragma unroll
                for (int pi = 0; pi < 4; ++pi) {
                    int t   = lane >> 3;
                    int row = wn * 64 + (2 * pi + (t >> 1)) * 8 + (lane & 7);
                    int g   = 2 * ks + (t & 1);
                    ldsm4(bfr[pi], bB + row * PITCH + g * 16);
                }
                #pragma unroll
                for (int mi = 0; mi < 2; ++mi)
                    #pragma unroll
                    for (int ni = 0; ni < 8; ++ni)
                        mma_bf16(d[mi][ni], afr[mi], &bfr[ni >> 1][(ni & 1) * 2]);
            }
            __syncthreads();
            if (c + 2 < NCHUNK) stage(c + 2);
        }

        // ---- fused epilogue: masked accumulation (polynomial exp, no MUFU) ----
        #pragma unroll
        for (int ni = 0; ni < 8; ++ni)
            #pragma unroll
            for (int q = 0; q < 2; ++q) {
                int jl  = wn * 64 + ni * 8 + ((lane & 3) << 1) + q;
                int jlb = slab[jl];
                int jg  = j0 + jl;
                #pragma unroll
                for (int mi = 0; mi < 2; ++mi)
                    #pragma unroll
                    for (int h = 0; h < 2; ++h) {
                        int r = mi * 2 + h;
                        float dv = d[mi][ni][h * 2 + q];
                        bool same = (jlb == rlab[r]);
                        // exp(x), |x| <= ~0.01: cubic Taylor, rel err ~2e-10
                        float x = dv * rc[r];
                        float p = fmaf(x, fmaf(x, fmaf(x, 0.16666667f, 0.5f), 1.0f), 1.0f);
                        if (!same) {
                            accN[r] += p;
                        } else {
                            int ig = i0 + wm * 32 + mi * 16 + h * 8 + (lane >> 2);
                            if (jg > ig) { accP[r] += dv; accL[r] += 1.0f; }
                        }
                    }
            }
    }

    // ---- deterministic reduction: 4 lanes sharing a row -> smem -> per-anchor ----
    #pragma unroll
    for (int r = 0; r < 4; ++r) {
        #pragma unroll
        for (int off = 1; off < 4; off <<= 1) {
            accN[r] += __shfl_xor_sync(0xffffffffu, accN[r], off);
            accP[r] += __shfl_xor_sync(0xffffffffu, accP[r], off);
            accL[r] += __shfl_xor_sync(0xffffffffu, accL[r], off);
        }
    }
    __syncthreads();
    if ((lane & 3) == 0) {
        #pragma unroll
        for (int r = 0; r < 4; ++r) {
            int iloc = wm * 32 + (r >> 1) * 16 + (r & 1) * 8 + (lane >> 2);
            sred[iloc][wn][0] = accN[r];
            sred[iloc][wn][1] = accP[r];
            sred[iloc][wn][2] = accL[r];
        }
    }
    __syncthreads();
    if (tid < 128) {
        float neg = sred[tid][0][0] + sred[tid][1][0];
        float pos = sred[tid][0][1] + sred[tid][1][1];
        float nl  = sred[tid][0][2] + sred[tid][1][2];
        int l  = lb[i0 + tid];
        int gs = g_cnt[b][l & (KNL - 1)];
        int nn = KS - gs;
        float per = 0.0f;
        if (nn > 0) {
            float ln = logf(neg);
            per = -(pos * SCALE_F - nl * ln) / (float)gs;
        }
        sred2[tid] = per;
    }
    __syncthreads();
    #pragma unroll 1
    for (int s = 64; s > 0; s >>= 1) {
        if (tid < s) sred2[tid] += sred2[tid + s];
        __syncthreads();
    }
    if (tid == 0) g_part[cta] = sred2[0];
}

// ---------------- kernel 4: deterministic final reduce ------------------------
__global__ void k_final(float* out) {
    __shared__ float s[256];
    int t = threadIdx.x;
    s[t] = g_part[t];
    __syncthreads();
    #pragma unroll 1
    for (int st = 128; st > 0; st >>= 1) {
        if (t < st) s[t] += s[t + st];
        __syncthreads();
    }
    if (t == 0) out[0] = s[0] / (float)KS;
}

// ---------------- launcher ----------------------------------------------------
extern "C" void kernel_launch(void* const* d_in, const int* in_sizes, int n_in,
                              void* d_out, int out_size) {
    (void)n_in; (void)out_size;
    // Select by element count: features = KB*KS*KD elements, labels = KB*KS.
    const void* p0 = d_in[0];
    const void* p1 = d_in[1];
    const float*    feat;
    const uint32_t* labw;
    if (in_sizes[0] >= in_sizes[1]) { feat = (const float*)p0; labw = (const uint32_t*)p1; }
    else                            { feat = (const float*)p1; labw = (const uint32_t*)p0; }
    float* out = (float*)d_out;

    size_t n4 = (size_t)KB * KS * KD / 4;
    k_preplab<<<1, 1024>>>(labw);
    k_convert<<<(unsigned)((n4 + 255) / 256), 256>>>(feat);
    k_count<<<KB, 256>>>();
    k_main<<<KB * 8, 256>>>();
    k_final<<<1, 256>>>(out);
}